// round 9
// baseline (speedup 1.0000x reference)
#include <cuda_runtime.h>
#include <math.h>

#define BE 64
#define NOCT 32
#define NSAMP 32768
#define TPB 256
#define ITEM_SAMP 2048
#define NBLK (BE * NSAMP / ITEM_SAMP)   // 1024 blocks, 1 item each
#define NCHUNK (NSAMP / ITEM_SAMP)      // 16 chunks per be
#define SPT 8

// Scratch (no allocation allowed). g_wmax slots each written exactly once per
// launch. g_done[be]: 0 at launch start (static init first time, reset by the
// last-finisher block thereafter) -> replay-deterministic.
__device__ float g_wmax[NBLK];
__device__ int   g_done[BE];

typedef unsigned long long ull;

__device__ __forceinline__ ull pk2(float x, float y) {
    ull r;
    asm("mov.b64 %0, {%1, %2};" : "=l"(r)
        : "r"(__float_as_uint(x)), "r"(__float_as_uint(y)));
    return r;
}
__device__ __forceinline__ void upk2(ull v, float& x, float& y) {
    unsigned a, b;
    asm("mov.b64 {%0, %1}, %2;" : "=r"(a), "=r"(b) : "l"(v));
    x = __uint_as_float(a);
    y = __uint_as_float(b);
}
__device__ __forceinline__ ull f2mul(ull a, ull b) {
    ull c; asm("mul.rn.f32x2 %0, %1, %2;" : "=l"(c) : "l"(a), "l"(b)); return c;
}
__device__ __forceinline__ ull f2add(ull a, ull b) {
    ull c; asm("add.rn.f32x2 %0, %1, %2;" : "=l"(c) : "l"(a), "l"(b)); return c;
}
__device__ __forceinline__ ull f2fma(ull a, ull b, ull c) {
    ull d; asm("fma.rn.f32x2 %0, %1, %2, %3;" : "=l"(d)
               : "l"(a), "l"(b), "l"(c)); return d;
}

// ---------------------------------------------------------------------------
// One kernel. Block = one (be, 2048-sample chunk), be-interleaved.
// Osc math identical to R8 (packed f32x2, lanewise IEEE RN == scalar):
// fl32(f*t) phase -> magic round -> exact 2-FMA Cody-Waite -> MUFU sin.
// The 16th finisher of each be normalizes that be in-place (no spinning).
// ---------------------------------------------------------------------------
__global__ void __launch_bounds__(TPB)
fused_kernel(const float* __restrict__ f0_in,
             const float* __restrict__ dec_in,
             const float* __restrict__ sp_in,
             float* __restrict__ out) {
    __shared__ float sf[NOCT];
    __shared__ float sa[NOCT];
    __shared__ int   snact;
    __shared__ float wm[TPB / 32];
    __shared__ int   s_last;

    const int be    = blockIdx.x & (BE - 1);
    const int chunk = blockIdx.x >> 6;           // 0..15
    const int tid   = threadIdx.x;
    const int lane  = tid & 31;

    // ---- setup: warp 0, lane-parallel, own be only (phase path bit-exact:
    //      lane o repeats the same sequential f32 fadd chain of length o+1)
    if (tid < 32) {
        const float MINF   = (float)(20.0 / 11025.0);
        const float FRANGE = (float)(3000.0 / 11025.0 - 20.0 / 11025.0);
        const float PI_F   = (float)3.14159265358979323846;
        const float RESF   = (float)((1.0 - 0.01) * 0.99);

        float f0  = fabsf(f0_in[be]);
        float fsc = __fmul_rn(__fadd_rn(MINF, __fmul_rn(f0, FRANGE)), PI_F);
        float sp  = sp_in[be];

        float x  = dec_in[be];
        float s1 = 1.0f / (1.0f + expf(-x));
        float s2 = 1.0f / (1.0f + expf(-s1));
        float d  = __fadd_rn(0.01f, __fmul_rn(s2, RESF));
        float ld = logf(__fadd_rn(d, 1e-12f));

        float fac = 0.0f;
        #pragma unroll
        for (int i = 0; i < NOCT; i++)
            if (i <= lane) fac = __fadd_rn(fac, sp);  // predicated seq cumsum
        float f0s = __fmul_rn(fsc, fac);
        sf[lane] = f0s;
        sa[lane] = __expf((float)(lane + 1) * ld);    // amp err ~1e-6, safe
        unsigned bal = __ballot_sync(0xFFFFFFFFu, f0s < 1.0f);
        if (lane == 0) snact = __popc(bal);           // monotone prefix mask
    }
    __syncthreads();
    const int nact = snact;

    // thread owns samples chunk*2048 + g*1024 + tid*4 + j (g=0..1, j=0..3)
    const float tb = (float)(chunk * ITEM_SAMP + tid * 4 + 1);
    ull TP[SPT / 2];
    TP[0] = pk2(tb,           tb + 1.0f);
    TP[1] = pk2(tb + 2.0f,    tb + 3.0f);
    TP[2] = pk2(tb + 1024.0f, tb + 1025.0f);
    TP[3] = pk2(tb + 1026.0f, tb + 1027.0f);

    const float INV2PI = 0.15915494309189535f;
    const float MAGIC  = 12582912.0f;                 // 1.5 * 2^23
    const float HI     = 6.2831855f;                  // fl32(2*pi)
    const float LO     = (float)(6.283185307179586476925286766559
                                 - (double)6.2831855f);
    const ull INV2PI2 = pk2(INV2PI, INV2PI);
    const ull MAGIC2  = pk2(MAGIC, MAGIC);
    const ull NMAG2   = pk2(-MAGIC, -MAGIC);
    const ull NHI2    = pk2(-HI, -HI);
    const ull NLO2    = pk2(-LO, -LO);

    ull ACC[SPT / 2];
    #pragma unroll
    for (int j = 0; j < SPT / 2; j++) ACC[j] = pk2(0.0f, 0.0f);

    #pragma unroll 1
    for (int o = 0; o < nact; o++) {
        const float f = sf[o];                         // broadcast LDS
        const float a = sa[o];
        const ull f2 = pk2(f, f);
        const ull a2 = pk2(a, a);
        #pragma unroll
        for (int j = 0; j < SPT / 2; j++) {
            ull p2 = f2mul(f2, TP[j]);                 // fl32(f*t) per lane
            ull q2 = f2fma(p2, INV2PI2, MAGIC2);
            ull k2 = f2add(q2, NMAG2);                 // round(p/2pi)
            ull r2 = f2fma(k2, NHI2, p2);
            r2     = f2fma(k2, NLO2, r2);              // exact CW reduce
            float r0, r1; upk2(r2, r0, r1);
            ull s2 = pk2(__sinf(r0), __sinf(r1));
            ACC[j] = f2fma(s2, a2, ACC[j]);
        }
    }

    float v0, v1, v2, v3, v4, v5, v6, v7;
    upk2(ACC[0], v0, v1); upk2(ACC[1], v2, v3);
    upk2(ACC[2], v4, v5); upk2(ACC[3], v6, v7);

    float4* o4 = (float4*)(out + be * NSAMP + chunk * ITEM_SAMP);
    float4 w0; w0.x = v0; w0.y = v1; w0.z = v2; w0.w = v3;
    float4 w1; w1.x = v4; w1.y = v5; w1.z = v6; w1.w = v7;
    o4[tid]       = w0;
    o4[tid + TPB] = w1;

    // block max-abs -> unique slot
    float m = fmaxf(fmaxf(fmaxf(fabsf(v0), fabsf(v1)),
                          fmaxf(fabsf(v2), fabsf(v3))),
                    fmaxf(fmaxf(fabsf(v4), fabsf(v5)),
                          fmaxf(fabsf(v6), fabsf(v7))));
    #pragma unroll
    for (int off = 16; off > 0; off >>= 1)
        m = fmaxf(m, __shfl_xor_sync(0xFFFFFFFFu, m, off));
    if (lane == 0) wm[tid >> 5] = m;

    // release: make this block's output + wmax visible, then arrive
    __threadfence();
    __syncthreads();
    if (tid == 0) {
        float mm = wm[0];
        #pragma unroll
        for (int j = 1; j < TPB / 32; j++) mm = fmaxf(mm, wm[j]);
        g_wmax[blockIdx.x] = mm;
        __threadfence();
        s_last = (atomicAdd(&g_done[be], 1) == NCHUNK - 1) ? 1 : 0;
    }
    __syncthreads();
    if (!s_last) return;

    // ---- last finisher of this be: whole be is written; normalize it ----
    __threadfence();                                   // acquire side
    float v = g_wmax[((lane & (NCHUNK - 1)) << 6) + be];
    #pragma unroll
    for (int off = 16; off > 0; off >>= 1)
        v = fmaxf(v, __shfl_xor_sync(0xFFFFFFFFu, v, off));
    const float inv = 1.0f / (v + 1e-8f);

    if (tid == 0) g_done[be] = 0;                      // replay reset

    float4* p = (float4*)(out + be * NSAMP);           // 8192 float4
    #pragma unroll 1
    for (int i = tid; i < NSAMP / 4; i += 4 * TPB) {
        // 4 front-batched L2 loads for MLP; bypass L1 (freshness + no reuse)
        float4 a = __ldcg(p + i);
        float4 b = __ldcg(p + i + TPB);
        float4 c = __ldcg(p + i + 2 * TPB);
        float4 d = __ldcg(p + i + 3 * TPB);
        a.x *= inv; a.y *= inv; a.z *= inv; a.w *= inv;
        b.x *= inv; b.y *= inv; b.z *= inv; b.w *= inv;
        c.x *= inv; c.y *= inv; c.z *= inv; c.w *= inv;
        d.x *= inv; d.y *= inv; d.z *= inv; d.w *= inv;
        __stcg(p + i,           a);
        __stcg(p + i + TPB,     b);
        __stcg(p + i + 2 * TPB, c);
        __stcg(p + i + 3 * TPB, d);
    }
}

extern "C" void kernel_launch(void* const* d_in, const int* in_sizes, int n_in,
                              void* d_out, int out_size) {
    const float* f0  = (const float*)d_in[0];
    const float* dec = (const float*)d_in[1];
    const float* sp  = (const float*)d_in[2];
    float* out = (float*)d_out;

    fused_kernel<<<NBLK, TPB>>>(f0, dec, sp, out);
}

// round 10
// speedup vs baseline: 1.3183x; 1.3183x over previous
#include <cuda_runtime.h>
#include <math.h>

#define BE 64
#define NOCT 32
#define NSAMP 32768
#define TPB 128
#define ITEM_SAMP 1024
#define NBLK (BE * NSAMP / ITEM_SAMP)   // 2048 blocks, 1 item each
#define SPT 8

// Per-item max scratch: every slot written exactly once per launch.
__device__ float g_wmax[NBLK];

typedef unsigned long long ull;

__device__ __forceinline__ ull pk2(float x, float y) {
    ull r;
    asm("mov.b64 %0, {%1, %2};" : "=l"(r)
        : "r"(__float_as_uint(x)), "r"(__float_as_uint(y)));
    return r;
}
__device__ __forceinline__ void upk2(ull v, float& x, float& y) {
    unsigned a, b;
    asm("mov.b64 {%0, %1}, %2;" : "=r"(a), "=r"(b) : "l"(v));
    x = __uint_as_float(a);
    y = __uint_as_float(b);
}
__device__ __forceinline__ ull f2mul(ull a, ull b) {
    ull c; asm("mul.rn.f32x2 %0, %1, %2;" : "=l"(c) : "l"(a), "l"(b)); return c;
}
__device__ __forceinline__ ull f2add(ull a, ull b) {
    ull c; asm("add.rn.f32x2 %0, %1, %2;" : "=l"(c) : "l"(a), "l"(b)); return c;
}
__device__ __forceinline__ ull f2fma(ull a, ull b, ull c) {
    ull d; asm("fma.rn.f32x2 %0, %1, %2, %3;" : "=l"(d)
               : "l"(a), "l"(b), "l"(c)); return d;
}

// ---------------------------------------------------------------------------
// Kernel A (identical to R8's proven osc): block = one (be, 1024-sample
// chunk), be-interleaved. Packed f32x2 math (lanewise IEEE RN == scalar):
// fl32(f*t) phase -> magic round -> exact 2-FMA Cody-Waite -> MUFU sin.
// ---------------------------------------------------------------------------
__global__ void __launch_bounds__(TPB)
osc_kernel(const float* __restrict__ f0_in,
           const float* __restrict__ dec_in,
           const float* __restrict__ sp_in,
           float* __restrict__ out) {
    __shared__ float sf[NOCT];
    __shared__ float sa[NOCT];
    __shared__ int   snact;
    __shared__ float wm[TPB / 32];

    const int be    = blockIdx.x & (BE - 1);
    const int chunk = blockIdx.x >> 6;
    const int tid   = threadIdx.x;
    const int lane  = tid & 31;

    // setup: warp 0, lane-parallel, own be only (phase path bit-exact:
    // lane o repeats the same sequential f32 fadd chain of length o+1)
    if (tid < 32) {
        const float MINF   = (float)(20.0 / 11025.0);
        const float FRANGE = (float)(3000.0 / 11025.0 - 20.0 / 11025.0);
        const float PI_F   = (float)3.14159265358979323846;
        const float RESF   = (float)((1.0 - 0.01) * 0.99);

        float f0  = fabsf(f0_in[be]);
        float fsc = __fmul_rn(__fadd_rn(MINF, __fmul_rn(f0, FRANGE)), PI_F);
        float sp  = sp_in[be];

        float x  = dec_in[be];
        float s1 = 1.0f / (1.0f + expf(-x));
        float s2 = 1.0f / (1.0f + expf(-s1));
        float d  = __fadd_rn(0.01f, __fmul_rn(s2, RESF));
        float ld = logf(__fadd_rn(d, 1e-12f));

        float fac = 0.0f;
        #pragma unroll
        for (int i = 0; i < NOCT; i++)
            if (i <= lane) fac = __fadd_rn(fac, sp);   // predicated seq cumsum
        float f0s = __fmul_rn(fsc, fac);
        sf[lane] = f0s;
        sa[lane] = __expf((float)(lane + 1) * ld);     // amp err ~1e-6, safe
        unsigned bal = __ballot_sync(0xFFFFFFFFu, f0s < 1.0f);
        if (lane == 0) snact = __popc(bal);            // monotone prefix mask
    }
    __syncthreads();
    const int nact = snact;

    // thread owns samples chunk*1024 + g*512 + tid*4 + j (g=0..1, j=0..3)
    const float tb = (float)(chunk * ITEM_SAMP + tid * 4 + 1);
    ull TP[SPT / 2];
    TP[0] = pk2(tb,          tb + 1.0f);
    TP[1] = pk2(tb + 2.0f,   tb + 3.0f);
    TP[2] = pk2(tb + 512.0f, tb + 513.0f);
    TP[3] = pk2(tb + 514.0f, tb + 515.0f);

    const float INV2PI = 0.15915494309189535f;
    const float MAGIC  = 12582912.0f;                  // 1.5 * 2^23
    const float HI     = 6.2831855f;                   // fl32(2*pi)
    const float LO     = (float)(6.283185307179586476925286766559
                                 - (double)6.2831855f);
    const ull INV2PI2 = pk2(INV2PI, INV2PI);
    const ull MAGIC2  = pk2(MAGIC, MAGIC);
    const ull NMAG2   = pk2(-MAGIC, -MAGIC);
    const ull NHI2    = pk2(-HI, -HI);
    const ull NLO2    = pk2(-LO, -LO);

    ull ACC[SPT / 2];
    #pragma unroll
    for (int j = 0; j < SPT / 2; j++) ACC[j] = pk2(0.0f, 0.0f);

    #pragma unroll 1
    for (int o = 0; o < nact; o++) {
        const float f = sf[o];                          // broadcast LDS
        const float a = sa[o];
        const ull f2 = pk2(f, f);
        const ull a2 = pk2(a, a);
        #pragma unroll
        for (int j = 0; j < SPT / 2; j++) {
            ull p2 = f2mul(f2, TP[j]);                  // fl32(f*t) per lane
            ull q2 = f2fma(p2, INV2PI2, MAGIC2);
            ull k2 = f2add(q2, NMAG2);                  // round(p/2pi)
            ull r2 = f2fma(k2, NHI2, p2);
            r2     = f2fma(k2, NLO2, r2);               // exact CW reduce
            float r0, r1; upk2(r2, r0, r1);
            ull s2 = pk2(__sinf(r0), __sinf(r1));
            ACC[j] = f2fma(s2, a2, ACC[j]);
        }
    }

    float v0, v1, v2, v3, v4, v5, v6, v7;
    upk2(ACC[0], v0, v1); upk2(ACC[1], v2, v3);
    upk2(ACC[2], v4, v5); upk2(ACC[3], v6, v7);

    float4* o4 = (float4*)(out + be * NSAMP + chunk * ITEM_SAMP);
    float4 w0; w0.x = v0; w0.y = v1; w0.z = v2; w0.w = v3;
    float4 w1; w1.x = v4; w1.y = v5; w1.z = v6; w1.w = v7;
    o4[tid]       = w0;
    o4[tid + TPB] = w1;

    // block max-abs -> one slot
    float m = fmaxf(fmaxf(fmaxf(fabsf(v0), fabsf(v1)),
                          fmaxf(fabsf(v2), fabsf(v3))),
                    fmaxf(fmaxf(fabsf(v4), fabsf(v5)),
                          fmaxf(fabsf(v6), fabsf(v7))));
    #pragma unroll
    for (int off = 16; off > 0; off >>= 1)
        m = fmaxf(m, __shfl_xor_sync(0xFFFFFFFFu, m, off));
    if (lane == 0) wm[tid >> 5] = m;
    __syncthreads();
    if (tid == 0) {
        float mm = fmaxf(fmaxf(wm[0], wm[1]), fmaxf(wm[2], wm[3]));
        g_wmax[blockIdx.x] = mm;
    }
}

// ---------------------------------------------------------------------------
// Kernel B: PDL secondary. Blocks may be distributed while osc drains; the
// grid-dependency sync blocks until osc's grid (and its memory) completes
// before any load. Then reduce 32 chunk-maxes per be and normalize in place.
// ---------------------------------------------------------------------------
__global__ void __launch_bounds__(256)
norm_kernel(float4* __restrict__ out4) {
    cudaGridDependencySynchronize();             // wait for osc + visibility

    const int be   = blockIdx.y;
    const int seg  = blockIdx.x;                 // 0..7, each 1024 float4
    const int tid  = threadIdx.x;
    const int lane = tid & 31;

    float v = g_wmax[(lane << 6) + be];          // 32 chunk maxes (be-interl.)
    #pragma unroll
    for (int off = 16; off > 0; off >>= 1)
        v = fmaxf(v, __shfl_xor_sync(0xFFFFFFFFu, v, off));
    const float inv = 1.0f / (v + 1e-8f);

    float4* p = out4 + be * (NSAMP / 4) + seg * 1024;
    float4 w0 = p[tid];
    float4 w1 = p[tid + 256];
    float4 w2 = p[tid + 512];
    float4 w3 = p[tid + 768];
    w0.x *= inv; w0.y *= inv; w0.z *= inv; w0.w *= inv;
    w1.x *= inv; w1.y *= inv; w1.z *= inv; w1.w *= inv;
    w2.x *= inv; w2.y *= inv; w2.z *= inv; w2.w *= inv;
    w3.x *= inv; w3.y *= inv; w3.z *= inv; w3.w *= inv;
    p[tid]       = w0;
    p[tid + 256] = w1;
    p[tid + 512] = w2;
    p[tid + 768] = w3;
}

extern "C" void kernel_launch(void* const* d_in, const int* in_sizes, int n_in,
                              void* d_out, int out_size) {
    const float* f0  = (const float*)d_in[0];
    const float* dec = (const float*)d_in[1];
    const float* sp  = (const float*)d_in[2];
    float* out = (float*)d_out;

    osc_kernel<<<NBLK, TPB>>>(f0, dec, sp, out);

    // norm with programmatic dependent launch: overlap its ramp with osc drain
    cudaLaunchConfig_t cfg = {};
    cfg.gridDim  = dim3(8, BE, 1);
    cfg.blockDim = dim3(256, 1, 1);
    cfg.dynamicSmemBytes = 0;
    cfg.stream = 0;                              // same (capture) stream
    cudaLaunchAttribute attr[1];
    attr[0].id = cudaLaunchAttributeProgrammaticStreamSerialization;
    attr[0].val.programmaticStreamSerializationAllowed = 1;
    cfg.attrs = attr;
    cfg.numAttrs = 1;
    cudaLaunchKernelEx(&cfg, norm_kernel, (float4*)out);
}